// round 2
// baseline (speedup 1.0000x reference)
#include <cuda_runtime.h>
#include <math.h>

// Inputs (metadata order): y[16M] f32, mu[16M] f32, std[16M] f32, idx[200*100] i32
// Output: 1 x f32 (KL scalar)

#define NUM_SAMPLES 200
#define KDOF 100

// Scratch (no device allocation allowed in kernel_launch).
__device__ float        g_q[NUM_SAMPLES];
__device__ unsigned int g_count = 0;   // returns to 0 at end of every launch

// Fused: 200 blocks x 128 threads. Each block computes q[s] for its sample;
// the LAST block to finish reduces all 200 q's -> mean, var(ddof=1), KL.
__global__ void __launch_bounds__(128) fused_chi2_kl_kernel(
    const float* __restrict__ y,
    const float* __restrict__ mu,
    const float* __restrict__ sd,
    const int*   __restrict__ idx,
    float*       __restrict__ out)
{
    const int s = blockIdx.x;
    const int t = threadIdx.x;

    // ---- Phase 1: per-sample chi-square statistic ----
    float v = 0.0f;
    if (t < KDOF) {
        const int i = idx[s * KDOF + t];
        // three independent loads -> MLP=3, latency fully pipelined
        const float d = (y[i] - mu[i]) / sd[i];
        v = d * d;
    }

    #pragma unroll
    for (int o = 16; o > 0; o >>= 1)
        v += __shfl_down_sync(0xFFFFFFFFu, v, o);

    __shared__ float sm[4];
    __shared__ int   s_last;
    if ((t & 31) == 0) sm[t >> 5] = v;
    __syncthreads();

    if (t == 0) {
        g_q[s] = sm[0] + sm[1] + sm[2] + sm[3];
        __threadfence();                      // publish g_q[s] before ticket
        unsigned int prev = atomicAdd(&g_count, 1u);
        s_last = (prev == NUM_SAMPLES - 1u) ? 1 : 0;
    }
    __syncthreads();

    if (!s_last) return;

    // ---- Phase 2 (last block only): reduce 200 q's -> KL ----
    __threadfence();                          // acquire: see all g_q writes

    // each thread t < 100 owns q[t] and q[t+100]
    float q0 = 0.0f, q1 = 0.0f;
    if (t < KDOF) {                           // KDOF == 100 == NUM_SAMPLES/2
        q0 = g_q[t];
        q1 = g_q[t + 100];
    }

    __shared__ float red[4];
    __shared__ float s_mean;

    // pass 1: mean
    float u = q0 + q1;
    #pragma unroll
    for (int o = 16; o > 0; o >>= 1)
        u += __shfl_down_sync(0xFFFFFFFFu, u, o);
    if ((t & 31) == 0) red[t >> 5] = u;
    __syncthreads();
    if (t == 0)
        s_mean = (red[0] + red[1] + red[2] + red[3]) / (float)NUM_SAMPLES;
    __syncthreads();

    // pass 2: sum of squared deviations
    const float mean = s_mean;
    float d0 = 0.0f, d1 = 0.0f;
    if (t < KDOF) { d0 = q0 - mean; d1 = q1 - mean; }
    u = d0 * d0 + d1 * d1;
    #pragma unroll
    for (int o = 16; o > 0; o >>= 1)
        u += __shfl_down_sync(0xFFFFFFFFu, u, o);
    if ((t & 31) == 0) red[t >> 5] = u;
    __syncthreads();

    if (t == 0) {
        const float var   = (red[0] + red[1] + red[2] + red[3])
                            / (float)(NUM_SAMPLES - 1);
        const float k     = (float)KDOF;
        const float two_k = 2.0f * k;
        const float dm    = mean - k;
        out[0] = 0.5f * logf(two_k / var)
               + (var + dm * dm) / (2.0f * two_k)
               - 0.5f;
        g_count = 0;                          // reset for next graph replay
    }
}

extern "C" void kernel_launch(void* const* d_in, const int* in_sizes, int n_in,
                              void* d_out, int out_size)
{
    const float* y   = (const float*)d_in[0];
    const float* mu  = (const float*)d_in[1];
    const float* sd  = (const float*)d_in[2];
    const int*   idx = (const int*)d_in[3];
    float* out = (float*)d_out;

    fused_chi2_kl_kernel<<<NUM_SAMPLES, 128>>>(y, mu, sd, idx, out);
}